// round 5
// baseline (speedup 1.0000x reference)
#include <cuda_runtime.h>
#include <cuda_bf16.h>

#define U      128
#define TT     96
#define NIN    6
#define NUNF   6
#define MOTOR  64
#define NCLS   100
#define BATCH  1024
#define NG     (BATCH/4)
#define LOG2E  1.4426950408889634f
#define EPSF   1e-8f
#define MAXPART 256

// ---------------- scratch (device globals; no allocation allowed) ----------
// Balanced segmented layout: global synapse list in target order, thread i
// owns entries [i*K, (i+1)*K). Entry e stored transposed at [(e%K)*U + e/K]
// so warp lanes read consecutive 16B -> one coalesced LDG.128 per entry.
// Entry = (A=0.5*sigma, B=-0.5*mu*sigma, hw=0.5*wp*erev (signed; hz=|hw|),
//          bitcast int: j | endflag<<7 | partial_slot<<8)
__device__ float4 g_synT[U*U];
__device__ int    g_Kd;                // entries per thread
__device__ int    g_poff[U+1];         // partial-slot ranges per target
__device__ float  g_cmt[U], g_gl[U], g_glv[U];
__device__ float  g_Cn[U], g_Cd[U];    // constant half-sums (tanh form)
__device__ float4 g_sensw[NIN*U];      // sensory (A, B, swp, swp*erev), ex2 form
__device__ float4 g_snum[NG*TT*U];     // sensory sums, float4 = 4 batches
__device__ float4 g_sden[NG*TT*U];
__device__ float  g_outs[BATCH*TT*MOTOR];

__device__ __forceinline__ float fast_ex2(float x){ float y; asm("ex2.approx.ftz.f32 %0, %1;" : "=f"(y) : "f"(x)); return y; }
__device__ __forceinline__ float fast_rcp(float x){ float y; asm("rcp.approx.ftz.f32 %0, %1;" : "=f"(y) : "f"(x)); return y; }
__device__ __forceinline__ float fast_tanh(float x){ float y; asm("tanh.approx.f32 %0, %1;" : "=f"(y) : "f"(x)); return y; }
__device__ __forceinline__ float softplusf(float x){ return (x > 20.f) ? x : log1pf(expf(x)); }

// ---------------- prep: constant folding + balanced segmented build --------
__global__ void prep_kernel(const float* gleak, const float* vleak, const float* cm,
                            const float* sigma, const float* mu, const float* w,
                            const float* erev, const float* ss, const float* smu,
                            const float* sw, const float* serev,
                            const float* mask, const float* smask)
{
    __shared__ int s_cnt[U];
    __shared__ int s_off[U+1];
    __shared__ int s_poff[U+1];
    __shared__ int s_K;
    int u = threadIdx.x;

    g_cmt[u] = softplusf(cm[u]) * (float)NUNF;
    float gl = softplusf(gleak[u]);
    g_gl[u]  = gl;
    g_glv[u] = gl * vleak[u];

    // sensory weights (ex2-form)
    for (int i = 0; i < NIN; i++) {
        float m  = smask[i*U + u];
        float sg = ss[i*U + u];
        float wp = softplusf(sw[i*U + u]) * m;
        float4 e;
        e.x = -sg * LOG2E;
        e.y = smu[i*U + u] * sg * LOG2E;
        e.z = wp;
        e.w = wp * serev[i*U + u];
        g_sensw[i*U + u] = e;
    }

    int cnt = 0;
    for (int j = 0; j < U; j++)
        if (mask[j*U + u] != 0.f) cnt++;
    s_cnt[u] = cnt;
    __syncthreads();

    if (u == 0) {
        int acc = 0;
        for (int v = 0; v < U; v++) { s_off[v] = acc; acc += s_cnt[v]; }
        s_off[U] = acc;
        int K = (acc + U - 1) / U;
        if (K < 1) K = 1;
        s_K = K;
        int p = 0;
        for (int v = 0; v < U; v++) {
            s_poff[v] = p;
            if (s_cnt[v] > 0) {
                int st = s_off[v], en = st + s_cnt[v] - 1;
                p += en / K - st / K + 1;
            }
        }
        s_poff[U] = p;
    }
    __syncthreads();

    int K   = s_K;
    int off = s_off[u];
    g_poff[u] = s_poff[u];
    if (u == 0) { g_poff[U] = s_poff[U]; g_Kd = K; }

    int i_first = off / K;
    float Cn = 0.f, Cd = 0.f;
    int local = 0;
    for (int j = 0; j < U; j++) {
        float m = mask[j*U + u];
        if (m != 0.f) {
            int e = off + local;
            int i = e / K, kk = e % K;
            float sg = sigma[j*U + u];
            float wp = softplusf(w[j*U + u]) * m;
            float hw = 0.5f * wp * erev[j*U + u];    // signed; |hw| = 0.5*wp
            bool endseg = (local == cnt - 1) || (((e + 1) % K) == 0);
            int ps = s_poff[u] + (i - i_first);
            int pk = j | (endseg ? 128 : 0) | (ps << 8);
            float4 ent;
            ent.x = 0.5f * sg;
            ent.y = -0.5f * mu[j*U + u] * sg;
            ent.z = hw;
            ent.w = __int_as_float(pk);
            g_synT[kk*U + i] = ent;
            Cn += hw;
            Cd += 0.5f * wp;
            local++;
        }
    }
    g_Cn[u] = Cn;
    g_Cd[u] = Cd;

    // padding entries: zero weight, no flag
    int NNZ = s_off[U];
    for (int e = NNZ + u; e < K*U; e += U) {
        int i = e / K, kk = e % K;
        float4 z; z.x = 0.f; z.y = 0.f; z.z = 0.f; z.w = __int_as_float(0);
        g_synT[kk*U + i] = z;
    }
}

// ---------------- sensory precompute: LayerNorm + sensory synapse sums -----
__global__ void sens_kernel(const float* __restrict__ x, const float* __restrict__ ln_g,
                            const float* __restrict__ ln_b, const float* __restrict__ in_w,
                            const float* __restrict__ in_b)
{
    int t = blockIdx.x;
    int b = blockIdx.y;
    int u = threadIdx.x;

    const float* xp = x + (b*TT + t)*NIN;
    float xv[NIN];
    float mean = 0.f;
    #pragma unroll
    for (int i = 0; i < NIN; i++) { xv[i] = xp[i]; mean += xv[i]; }
    mean *= (1.f/NIN);
    float var = 0.f;
    #pragma unroll
    for (int i = 0; i < NIN; i++) { float d = xv[i] - mean; var += d*d; }
    var *= (1.f/NIN);
    float inv = rsqrtf(var + 1e-5f);

    float inp[NIN];
    #pragma unroll
    for (int i = 0; i < NIN; i++)
        inp[i] = ((xv[i]-mean)*inv*ln_g[i] + ln_b[i]) * in_w[i] + in_b[i];

    float num = 0.f, den = 0.f;
    #pragma unroll
    for (int i = 0; i < NIN; i++) {
        float4 S = g_sensw[i*U + u];
        float e = fast_ex2(fmaf(inp[i], S.x, S.y));
        float r = fast_rcp(1.f + e);
        num = fmaf(S.w, r, num);
        den = fmaf(S.z, r, den);
    }
    int g = b >> 2, lane = b & 3;
    int idx = ((g*TT + t)*U + u)*4 + lane;
    ((float*)g_snum)[idx] = num;
    ((float*)g_sden)[idx] = den;
}

// ---------------- main LTC recurrence (balanced segmented) -----------------
__global__ void __launch_bounds__(U) ltc_main(const float* __restrict__ out_w,
                                              const float* __restrict__ out_b)
{
    __shared__ float4 vbuf[2][U];
    __shared__ float4 s_pn[MAXPART];
    __shared__ float4 s_pd[MAXPART];
    __shared__ float  s_ow[MOTOR], s_ob[MOTOR];

    int u = threadIdx.x;
    int g = blockIdx.x;

    float cmt = g_cmt[u], gl = g_gl[u], glv = g_glv[u];
    float Cn = g_Cn[u],   Cd = g_Cd[u];
    int pbeg = g_poff[u], pend = g_poff[u+1];
    int K = g_Kd;

    if (u < MOTOR) { s_ow[u] = out_w[u]; s_ob[u] = out_b[u]; }

    vbuf[0][u] = make_float4(0.f, 0.f, 0.f, 0.f);
    __syncthreads();
    int cur = 0;

    const float4* __restrict__ snum = g_snum + g*TT*U;
    const float4* __restrict__ sden = g_sden + g*TT*U;
    float dc = cmt + gl + Cd;
    float nc = glv + Cn;

    int m  = u & 63;
    int q  = u >> 6;
    int b0 = g * 4;

    for (int t = 0; t < TT; t++) {
        float4 sn = snum[t*U + u];
        float4 sd = sden[t*U + u];
        float bnx = nc + sn.x, bny = nc + sn.y, bnz = nc + sn.z, bnw = nc + sn.w;
        float bdx = dc + sd.x, bdy = dc + sd.y, bdz = dc + sd.z, bdw = dc + sd.w;

        #pragma unroll 1
        for (int f = 0; f < NUNF; f++) {
            // --- compute phase: uniform K iterations per thread ---
            float nx=0.f, ny=0.f, nz=0.f, nw=0.f;
            float dx=0.f, dy=0.f, dz=0.f, dw=0.f;
            for (int k = 0; k < K; k++) {
                float4 W = __ldg(&g_synT[k*U + u]);
                int pk = __float_as_int(W.w);
                float4 vj = vbuf[cur][pk & 127];
                float hz = fabsf(W.z);
                float t0 = fast_tanh(fmaf(vj.x, W.x, W.y));
                float t1 = fast_tanh(fmaf(vj.y, W.x, W.y));
                float t2 = fast_tanh(fmaf(vj.z, W.x, W.y));
                float t3 = fast_tanh(fmaf(vj.w, W.x, W.y));
                nx = fmaf(W.z, t0, nx); dx = fmaf(hz, t0, dx);
                ny = fmaf(W.z, t1, ny); dy = fmaf(hz, t1, dy);
                nz = fmaf(W.z, t2, nz); dz = fmaf(hz, t2, dz);
                nw = fmaf(W.z, t3, nw); dw = fmaf(hz, t3, dw);
                if (pk & 128) {
                    int ps = pk >> 8;
                    s_pn[ps] = make_float4(nx, ny, nz, nw);
                    s_pd[ps] = make_float4(dx, dy, dz, dw);
                    nx=ny=nz=nw=0.f; dx=dy=dz=dw=0.f;
                }
            }
            __syncthreads();

            // --- reduce phase: combine partials for target u ---
            float4 vu = vbuf[cur][u];
            float Nx = fmaf(cmt, vu.x, bnx);
            float Ny = fmaf(cmt, vu.y, bny);
            float Nz = fmaf(cmt, vu.z, bnz);
            float Nw = fmaf(cmt, vu.w, bnw);
            float Dx = bdx, Dy = bdy, Dz = bdz, Dw = bdw;
            for (int p = pbeg; p < pend; p++) {
                float4 a = s_pn[p];
                float4 bq = s_pd[p];
                Nx += a.x;  Ny += a.y;  Nz += a.z;  Nw += a.w;
                Dx += bq.x; Dy += bq.y; Dz += bq.z; Dw += bq.w;
            }
            float4 vn;
            vn.x = Nx * fast_rcp(Dx + EPSF);
            vn.y = Ny * fast_rcp(Dy + EPSF);
            vn.z = Nz * fast_rcp(Dz + EPSF);
            vn.w = Nw * fast_rcp(Dw + EPSF);
            vbuf[cur ^ 1][u] = vn;
            __syncthreads();
            cur ^= 1;
        }

        // coalesced motor-output write
        {
            float4 vv = vbuf[cur][m];
            float o0 = (q == 0) ? vv.x : vv.y;
            float o1 = (q == 0) ? vv.z : vv.w;
            float ww = s_ow[m], bb = s_ob[m];
            g_outs[((b0 + q    )*TT + t)*MOTOR + m] = fmaf(o0, ww, bb);
            g_outs[((b0 + q + 2)*TT + t)*MOTOR + m] = fmaf(o1, ww, bb);
        }
    }
}

// ---------------- attention pooling + classifier ----------------------------
__global__ void __launch_bounds__(128) attn_kernel(
    const float* __restrict__ aw1, const float* __restrict__ ab1,
    const float* __restrict__ aw2, const float* __restrict__ cw1,
    const float* __restrict__ cb1, const float* __restrict__ cw2,
    const float* __restrict__ cb2, float* __restrict__ out)
{
    __shared__ float so[TT][MOTOR+1];
    __shared__ float w1[MOTOR*32];
    __shared__ float sc[TT];
    __shared__ float ctx[MOTOR];
    __shared__ float hid[128];

    int b = blockIdx.x, tid = threadIdx.x;

    for (int i = tid; i < TT*MOTOR; i += 128)
        so[i/MOTOR][i%MOTOR] = g_outs[b*TT*MOTOR + i];
    for (int i = tid; i < MOTOR*32; i += 128)
        w1[i] = aw1[i];
    __syncthreads();

    if (tid < TT) {
        float acc = 0.f;
        for (int h = 0; h < 32; h++) {
            float s = ab1[h];
            #pragma unroll 8
            for (int uu = 0; uu < MOTOR; uu++)
                s = fmaf(so[tid][uu], w1[uu*32 + h], s);
            s = fmaxf(s, 0.f);
            acc = fmaf(s, aw2[h], acc);
        }
        sc[tid] = acc;
    }
    __syncthreads();

    if (tid == 0) {
        float m = -1e30f;
        for (int t = 0; t < TT; t++) m = fmaxf(m, sc[t]);
        float s = 0.f;
        for (int t = 0; t < TT; t++) { float e = __expf(sc[t]-m); sc[t] = e; s += e; }
        float invs = 1.f / s;
        for (int t = 0; t < TT; t++) sc[t] *= invs;
    }
    __syncthreads();

    if (tid < MOTOR) {
        float a = 0.f;
        for (int t = 0; t < TT; t++) a = fmaf(sc[t], so[t][tid], a);
        ctx[tid] = a;
    }
    __syncthreads();

    {
        float s = cb1[tid];
        for (int uu = 0; uu < MOTOR; uu++)
            s = fmaf(ctx[uu], cw1[uu*128 + tid], s);
        hid[tid] = fmaxf(s, 0.f);
    }
    __syncthreads();

    if (tid < NCLS) {
        float s = cb2[tid];
        for (int h = 0; h < 128; h++)
            s = fmaf(hid[h], cw2[h*NCLS + tid], s);
        out[b*NCLS + tid] = s;
    }
}

// ---------------- launch ----------------------------------------------------
extern "C" void kernel_launch(void* const* d_in, const int* in_sizes, int n_in,
                              void* d_out, int out_size)
{
    const float* x        = (const float*)d_in[0];
    const float* ln_g     = (const float*)d_in[1];
    const float* ln_b     = (const float*)d_in[2];
    const float* gleak    = (const float*)d_in[3];
    const float* vleak    = (const float*)d_in[4];
    const float* cm       = (const float*)d_in[5];
    const float* sigma    = (const float*)d_in[6];
    const float* mu       = (const float*)d_in[7];
    const float* w        = (const float*)d_in[8];
    const float* erev     = (const float*)d_in[9];
    const float* ssig     = (const float*)d_in[10];
    const float* smu      = (const float*)d_in[11];
    const float* sw       = (const float*)d_in[12];
    const float* serev    = (const float*)d_in[13];
    const float* in_w     = (const float*)d_in[14];
    const float* in_b     = (const float*)d_in[15];
    const float* out_w    = (const float*)d_in[16];
    const float* out_b    = (const float*)d_in[17];
    const float* aw1      = (const float*)d_in[18];
    const float* ab1      = (const float*)d_in[19];
    const float* aw2      = (const float*)d_in[20];
    const float* cw1      = (const float*)d_in[21];
    const float* cb1      = (const float*)d_in[22];
    const float* cw2      = (const float*)d_in[23];
    const float* cb2      = (const float*)d_in[24];
    const float* mask     = (const float*)d_in[25];
    const float* smask    = (const float*)d_in[26];

    prep_kernel<<<1, U>>>(gleak, vleak, cm, sigma, mu, w, erev,
                          ssig, smu, sw, serev, mask, smask);
    sens_kernel<<<dim3(TT, BATCH), U>>>(x, ln_g, ln_b, in_w, in_b);
    ltc_main<<<NG, U>>>(out_w, out_b);
    attn_kernel<<<BATCH, 128>>>(aw1, ab1, aw2, cw1, cb1, cw2, cb2, (float*)d_out);
}

// round 6
// speedup vs baseline: 1.0248x; 1.0248x over previous
#include <cuda_runtime.h>
#include <cuda_bf16.h>

#define U      128
#define TT     96
#define NIN    6
#define NUNF   6
#define MOTOR  64
#define NCLS   100
#define BATCH  1024
#define NG8    (BATCH/8)
#define LOG2E  1.4426950408889634f
#define EPSF   1e-8f

// ---------------- scratch (device globals; no allocation allowed) ----------
// Per-target transposed table padded to uniform Kmax:
// entry (k, target u) at g_synT[k*U + u] = (A=0.5*sigma, B=-0.5*mu*sigma,
// hw=0.5*wp*erev, bitcast int j). Padding entries have hw=0 -> contribute 0.
__device__ float4 g_synT[U*U];
__device__ int    g_Kmax;
__device__ float  g_cmt[U], g_gl[U], g_glv[U];
__device__ float  g_Cn[U], g_Cd[U];       // constant half-sums (tanh identity)
__device__ float4 g_sensw[NIN*U];         // sensory (A, B, swp, swp*erev), ex2 form
__device__ float4 g_snum[NG8*TT*U*2];     // sensory sums; [..][u][h], h=batch-half
__device__ float4 g_sden[NG8*TT*U*2];
__device__ float  g_outs[BATCH*TT*MOTOR];

__device__ __forceinline__ float fast_ex2(float x){ float y; asm("ex2.approx.ftz.f32 %0, %1;" : "=f"(y) : "f"(x)); return y; }
__device__ __forceinline__ float fast_rcp(float x){ float y; asm("rcp.approx.ftz.f32 %0, %1;" : "=f"(y) : "f"(x)); return y; }
__device__ __forceinline__ float fast_tanh(float x){ float y; asm("tanh.approx.f32 %0, %1;" : "=f"(y) : "f"(x)); return y; }
__device__ __forceinline__ float softplusf(float x){ return (x > 20.f) ? x : log1pf(expf(x)); }

// ---------------- prep: constant folding + uniform padded table ------------
__global__ void prep_kernel(const float* gleak, const float* vleak, const float* cm,
                            const float* sigma, const float* mu, const float* w,
                            const float* erev, const float* ss, const float* smu,
                            const float* sw, const float* serev,
                            const float* mask, const float* smask)
{
    __shared__ int s_cnt[U];
    __shared__ int s_Kmax;
    int u = threadIdx.x;

    g_cmt[u] = softplusf(cm[u]) * (float)NUNF;
    float gl = softplusf(gleak[u]);
    g_gl[u]  = gl;
    g_glv[u] = gl * vleak[u];

    // sensory weights (ex2 form)
    for (int i = 0; i < NIN; i++) {
        float m  = smask[i*U + u];
        float sg = ss[i*U + u];
        float wp = softplusf(sw[i*U + u]) * m;
        float4 e;
        e.x = -sg * LOG2E;
        e.y = smu[i*U + u] * sg * LOG2E;
        e.z = wp;
        e.w = wp * serev[i*U + u];
        g_sensw[i*U + u] = e;
    }

    int cnt = 0;
    for (int j = 0; j < U; j++)
        if (mask[j*U + u] != 0.f) cnt++;
    s_cnt[u] = cnt;
    __syncthreads();
    if (u == 0) {
        int mx = 1;
        for (int v = 0; v < U; v++) if (s_cnt[v] > mx) mx = s_cnt[v];
        s_Kmax = mx;
        g_Kmax = mx;
    }
    __syncthreads();
    int Kmax = s_Kmax;

    float Cn = 0.f, Cd = 0.f;
    int k = 0;
    for (int j = 0; j < U; j++) {
        float m = mask[j*U + u];
        if (m != 0.f) {
            float sg = sigma[j*U + u];
            float wp = softplusf(w[j*U + u]) * m;
            float hw = 0.5f * wp * erev[j*U + u];    // |hw| = 0.5*wp
            float4 ent;
            ent.x = 0.5f * sg;
            ent.y = -0.5f * mu[j*U + u] * sg;
            ent.z = hw;
            ent.w = __int_as_float(j);
            g_synT[k*U + u] = ent;
            Cn += hw;
            Cd += 0.5f * wp;
            k++;
        }
    }
    g_Cn[u] = Cn;
    g_Cd[u] = Cd;
    // padding: zero weight, j=0 (tanh contribution multiplied by 0)
    for (; k < Kmax; k++) {
        float4 z; z.x = 0.f; z.y = 0.f; z.z = 0.f; z.w = __int_as_float(0);
        g_synT[k*U + u] = z;
    }
}

// ---------------- sensory precompute: LayerNorm + sensory synapse sums -----
__global__ void sens_kernel(const float* __restrict__ x, const float* __restrict__ ln_g,
                            const float* __restrict__ ln_b, const float* __restrict__ in_w,
                            const float* __restrict__ in_b)
{
    int t = blockIdx.x;
    int b = blockIdx.y;
    int u = threadIdx.x;

    const float* xp = x + (b*TT + t)*NIN;
    float xv[NIN];
    float mean = 0.f;
    #pragma unroll
    for (int i = 0; i < NIN; i++) { xv[i] = xp[i]; mean += xv[i]; }
    mean *= (1.f/NIN);
    float var = 0.f;
    #pragma unroll
    for (int i = 0; i < NIN; i++) { float d = xv[i] - mean; var += d*d; }
    var *= (1.f/NIN);
    float inv = rsqrtf(var + 1e-5f);

    float inp[NIN];
    #pragma unroll
    for (int i = 0; i < NIN; i++)
        inp[i] = ((xv[i]-mean)*inv*ln_g[i] + ln_b[i]) * in_w[i] + in_b[i];

    float num = 0.f, den = 0.f;
    #pragma unroll
    for (int i = 0; i < NIN; i++) {
        float4 S = g_sensw[i*U + u];
        float e = fast_ex2(fmaf(inp[i], S.x, S.y));
        float r = fast_rcp(1.f + e);
        num = fmaf(S.w, r, num);
        den = fmaf(S.z, r, den);
    }
    // batch b -> group g = b>>3, half h = (b>>2)&1, slot s = b&3
    int g = b >> 3, h = (b >> 2) & 1, s = b & 3;
    int idx = ((((g*TT + t)*U + u)*2) + h)*4 + s;
    ((float*)g_snum)[idx] = num;
    ((float*)g_sden)[idx] = den;
}

// ---------------- main LTC recurrence: 8 batches/thread, uniform Kmax ------
__global__ void __launch_bounds__(U) ltc_main(const float* __restrict__ out_w,
                                              const float* __restrict__ out_b)
{
    __shared__ float4 vA[2][U];      // batches 0-3 of this group
    __shared__ float4 vB[2][U];      // batches 4-7
    __shared__ float  s_ow[MOTOR], s_ob[MOTOR];

    int u = threadIdx.x;
    int g = blockIdx.x;

    float cmt = g_cmt[u], gl = g_gl[u], glv = g_glv[u];
    float Cn = g_Cn[u],   Cd = g_Cd[u];
    int Kmax = g_Kmax;

    if (u < MOTOR) { s_ow[u] = out_w[u]; s_ob[u] = out_b[u]; }

    vA[0][u] = make_float4(0.f, 0.f, 0.f, 0.f);
    vB[0][u] = make_float4(0.f, 0.f, 0.f, 0.f);
    __syncthreads();
    int cur = 0;

    const float4* __restrict__ snum = g_snum + g*TT*U*2;
    const float4* __restrict__ sden = g_sden + g*TT*U*2;
    float dc = cmt + gl + Cd;
    float nc = glv + Cn;

    int m  = u & 63;
    int h  = u >> 6;       // 0: write batches 0-3, 1: batches 4-7
    int b0 = g * 8;

    for (int t = 0; t < TT; t++) {
        float4 snA = snum[(t*U + u)*2 + 0];
        float4 snB = snum[(t*U + u)*2 + 1];
        float4 sdA = sden[(t*U + u)*2 + 0];
        float4 sdB = sden[(t*U + u)*2 + 1];
        float bn[8], bd[8];
        bn[0]=nc+snA.x; bn[1]=nc+snA.y; bn[2]=nc+snA.z; bn[3]=nc+snA.w;
        bn[4]=nc+snB.x; bn[5]=nc+snB.y; bn[6]=nc+snB.z; bn[7]=nc+snB.w;
        bd[0]=dc+sdA.x; bd[1]=dc+sdA.y; bd[2]=dc+sdA.z; bd[3]=dc+sdA.w;
        bd[4]=dc+sdB.x; bd[5]=dc+sdB.y; bd[6]=dc+sdB.z; bd[7]=dc+sdB.w;

        #pragma unroll 1
        for (int f = 0; f < NUNF; f++) {
            float4 vuA = vA[cur][u];
            float4 vuB = vB[cur][u];
            float n0 = fmaf(cmt, vuA.x, bn[0]);
            float n1 = fmaf(cmt, vuA.y, bn[1]);
            float n2 = fmaf(cmt, vuA.z, bn[2]);
            float n3 = fmaf(cmt, vuA.w, bn[3]);
            float n4 = fmaf(cmt, vuB.x, bn[4]);
            float n5 = fmaf(cmt, vuB.y, bn[5]);
            float n6 = fmaf(cmt, vuB.z, bn[6]);
            float n7 = fmaf(cmt, vuB.w, bn[7]);
            float d0=bd[0], d1=bd[1], d2=bd[2], d3=bd[3];
            float d4=bd[4], d5=bd[5], d6=bd[6], d7=bd[7];

            #pragma unroll 2
            for (int k = 0; k < Kmax; k++) {
                float4 W = __ldg(&g_synT[k*U + u]);
                int j = __float_as_int(W.w);
                float4 aJ = vA[cur][j];
                float4 bJ = vB[cur][j];
                float hz = fabsf(W.z);
                float t0 = fast_tanh(fmaf(aJ.x, W.x, W.y));
                float t1 = fast_tanh(fmaf(aJ.y, W.x, W.y));
                float t2 = fast_tanh(fmaf(aJ.z, W.x, W.y));
                float t3 = fast_tanh(fmaf(aJ.w, W.x, W.y));
                float t4 = fast_tanh(fmaf(bJ.x, W.x, W.y));
                float t5 = fast_tanh(fmaf(bJ.y, W.x, W.y));
                float t6 = fast_tanh(fmaf(bJ.z, W.x, W.y));
                float t7 = fast_tanh(fmaf(bJ.w, W.x, W.y));
                n0 = fmaf(W.z, t0, n0); d0 = fmaf(hz, t0, d0);
                n1 = fmaf(W.z, t1, n1); d1 = fmaf(hz, t1, d1);
                n2 = fmaf(W.z, t2, n2); d2 = fmaf(hz, t2, d2);
                n3 = fmaf(W.z, t3, n3); d3 = fmaf(hz, t3, d3);
                n4 = fmaf(W.z, t4, n4); d4 = fmaf(hz, t4, d4);
                n5 = fmaf(W.z, t5, n5); d5 = fmaf(hz, t5, d5);
                n6 = fmaf(W.z, t6, n6); d6 = fmaf(hz, t6, d6);
                n7 = fmaf(W.z, t7, n7); d7 = fmaf(hz, t7, d7);
            }
            float4 wA, wB;
            wA.x = n0 * fast_rcp(d0 + EPSF);
            wA.y = n1 * fast_rcp(d1 + EPSF);
            wA.z = n2 * fast_rcp(d2 + EPSF);
            wA.w = n3 * fast_rcp(d3 + EPSF);
            wB.x = n4 * fast_rcp(d4 + EPSF);
            wB.y = n5 * fast_rcp(d5 + EPSF);
            wB.z = n6 * fast_rcp(d6 + EPSF);
            wB.w = n7 * fast_rcp(d7 + EPSF);
            __syncthreads();           // everyone done reading vbuf[cur]
            vA[cur ^ 1][u] = wA;
            vB[cur ^ 1][u] = wB;
            __syncthreads();
            cur ^= 1;
        }

        // coalesced motor-output write: warps 0-1 -> batches 0-3, warps 2-3 -> 4-7
        {
            float4 vv = (h == 0) ? vA[cur][m] : vB[cur][m];
            float ww = s_ow[m], bb = s_ob[m];
            g_outs[((b0 + 4*h + 0)*TT + t)*MOTOR + m] = fmaf(vv.x, ww, bb);
            g_outs[((b0 + 4*h + 1)*TT + t)*MOTOR + m] = fmaf(vv.y, ww, bb);
            g_outs[((b0 + 4*h + 2)*TT + t)*MOTOR + m] = fmaf(vv.z, ww, bb);
            g_outs[((b0 + 4*h + 3)*TT + t)*MOTOR + m] = fmaf(vv.w, ww, bb);
        }
    }
}

// ---------------- attention pooling + classifier ----------------------------
__global__ void __launch_bounds__(128) attn_kernel(
    const float* __restrict__ aw1, const float* __restrict__ ab1,
    const float* __restrict__ aw2, const float* __restrict__ cw1,
    const float* __restrict__ cb1, const float* __restrict__ cw2,
    const float* __restrict__ cb2, float* __restrict__ out)
{
    __shared__ float so[TT][MOTOR+1];
    __shared__ float w1[MOTOR*32];
    __shared__ float sc[TT];
    __shared__ float ctx[MOTOR];
    __shared__ float hid[128];

    int b = blockIdx.x, tid = threadIdx.x;

    for (int i = tid; i < TT*MOTOR; i += 128)
        so[i/MOTOR][i%MOTOR] = g_outs[b*TT*MOTOR + i];
    for (int i = tid; i < MOTOR*32; i += 128)
        w1[i] = aw1[i];
    __syncthreads();

    if (tid < TT) {
        float acc = 0.f;
        for (int hh = 0; hh < 32; hh++) {
            float s = ab1[hh];
            #pragma unroll 8
            for (int uu = 0; uu < MOTOR; uu++)
                s = fmaf(so[tid][uu], w1[uu*32 + hh], s);
            s = fmaxf(s, 0.f);
            acc = fmaf(s, aw2[hh], acc);
        }
        sc[tid] = acc;
    }
    __syncthreads();

    if (tid == 0) {
        float mm = -1e30f;
        for (int t = 0; t < TT; t++) mm = fmaxf(mm, sc[t]);
        float s = 0.f;
        for (int t = 0; t < TT; t++) { float e = __expf(sc[t]-mm); sc[t] = e; s += e; }
        float invs = 1.f / s;
        for (int t = 0; t < TT; t++) sc[t] *= invs;
    }
    __syncthreads();

    if (tid < MOTOR) {
        float a = 0.f;
        for (int t = 0; t < TT; t++) a = fmaf(sc[t], so[t][tid], a);
        ctx[tid] = a;
    }
    __syncthreads();

    {
        float s = cb1[tid];
        for (int uu = 0; uu < MOTOR; uu++)
            s = fmaf(ctx[uu], cw1[uu*128 + tid], s);
        hid[tid] = fmaxf(s, 0.f);
    }
    __syncthreads();

    if (tid < NCLS) {
        float s = cb2[tid];
        for (int hh = 0; hh < 128; hh++)
            s = fmaf(hid[hh], cw2[hh*NCLS + tid], s);
        out[b*NCLS + tid] = s;
    }
}

// ---------------- launch ----------------------------------------------------
extern "C" void kernel_launch(void* const* d_in, const int* in_sizes, int n_in,
                              void* d_out, int out_size)
{
    const float* x        = (const float*)d_in[0];
    const float* ln_g     = (const float*)d_in[1];
    const float* ln_b     = (const float*)d_in[2];
    const float* gleak    = (const float*)d_in[3];
    const float* vleak    = (const float*)d_in[4];
    const float* cm       = (const float*)d_in[5];
    const float* sigma    = (const float*)d_in[6];
    const float* mu       = (const float*)d_in[7];
    const float* w        = (const float*)d_in[8];
    const float* erev     = (const float*)d_in[9];
    const float* ssig     = (const float*)d_in[10];
    const float* smu      = (const float*)d_in[11];
    const float* sw       = (const float*)d_in[12];
    const float* serev    = (const float*)d_in[13];
    const float* in_w     = (const float*)d_in[14];
    const float* in_b     = (const float*)d_in[15];
    const float* out_w    = (const float*)d_in[16];
    const float* out_b    = (const float*)d_in[17];
    const float* aw1      = (const float*)d_in[18];
    const float* ab1      = (const float*)d_in[19];
    const float* aw2      = (const float*)d_in[20];
    const float* cw1      = (const float*)d_in[21];
    const float* cb1      = (const float*)d_in[22];
    const float* cw2      = (const float*)d_in[23];
    const float* cb2      = (const float*)d_in[24];
    const float* mask     = (const float*)d_in[25];
    const float* smask    = (const float*)d_in[26];

    prep_kernel<<<1, U>>>(gleak, vleak, cm, sigma, mu, w, erev,
                          ssig, smu, sw, serev, mask, smask);
    sens_kernel<<<dim3(TT, BATCH), U>>>(x, ln_g, ln_b, in_w, in_b);
    ltc_main<<<NG8, U>>>(out_w, out_b);
    attn_kernel<<<BATCH, 128>>>(aw1, ab1, aw2, cw1, cb1, cw2, cb2, (float*)d_out);
}

// round 7
// speedup vs baseline: 1.7216x; 1.6799x over previous
#include <cuda_runtime.h>
#include <cuda_bf16.h>

#define U      128
#define TT     96
#define NIN    6
#define NUNF   6
#define MOTOR  64
#define NCLS   100
#define BATCH  1024
#define NG8    (BATCH/8)
#define LOG2E  1.4426950408889634f
#define EPSF   1e-8f
#define KSPLIT 4

// ---------------- scratch (device globals; no allocation allowed) ----------
// Per-target transposed table padded to uniform Kpad = KSPLIT*ceil(Kmax/KSPLIT):
// entry (k, target u) at g_synT[k*U + u] = (A=0.5*sigma, B=-0.5*mu*sigma,
// hw=0.5*wp*erev, bitcast int j). Padding entries have hw=0 -> contribute 0.
__device__ float4 g_synT[U*U];
__device__ int    g_Kq;                   // entries per thread = Kpad/KSPLIT
__device__ float  g_cmt[U], g_gl[U], g_glv[U];
__device__ float  g_Cn[U], g_Cd[U];       // constant half-sums (tanh identity)
__device__ float4 g_sensw[NIN*U];         // sensory (A, B, swp, swp*erev), ex2 form
__device__ float4 g_snum[NG8*TT*U*2];     // sensory sums; [g][t][u][h], h=batch-half
__device__ float4 g_sden[NG8*TT*U*2];
__device__ float  g_outs[BATCH*TT*MOTOR];

__device__ __forceinline__ float fast_ex2(float x){ float y; asm("ex2.approx.ftz.f32 %0, %1;" : "=f"(y) : "f"(x)); return y; }
__device__ __forceinline__ float fast_rcp(float x){ float y; asm("rcp.approx.ftz.f32 %0, %1;" : "=f"(y) : "f"(x)); return y; }
__device__ __forceinline__ float fast_tanh(float x){ float y; asm("tanh.approx.f32 %0, %1;" : "=f"(y) : "f"(x)); return y; }
__device__ __forceinline__ float softplusf(float x){ return (x > 20.f) ? x : log1pf(expf(x)); }

// ---------------- prep: constant folding + uniform padded table ------------
__global__ void prep_kernel(const float* gleak, const float* vleak, const float* cm,
                            const float* sigma, const float* mu, const float* w,
                            const float* erev, const float* ss, const float* smu,
                            const float* sw, const float* serev,
                            const float* mask, const float* smask)
{
    __shared__ int s_cnt[U];
    __shared__ int s_Kpad;
    int u = threadIdx.x;

    g_cmt[u] = softplusf(cm[u]) * (float)NUNF;
    float gl = softplusf(gleak[u]);
    g_gl[u]  = gl;
    g_glv[u] = gl * vleak[u];

    // sensory weights (ex2 form)
    for (int i = 0; i < NIN; i++) {
        float m  = smask[i*U + u];
        float sg = ss[i*U + u];
        float wp = softplusf(sw[i*U + u]) * m;
        float4 e;
        e.x = -sg * LOG2E;
        e.y = smu[i*U + u] * sg * LOG2E;
        e.z = wp;
        e.w = wp * serev[i*U + u];
        g_sensw[i*U + u] = e;
    }

    int cnt = 0;
    for (int j = 0; j < U; j++)
        if (mask[j*U + u] != 0.f) cnt++;
    s_cnt[u] = cnt;
    __syncthreads();
    if (u == 0) {
        int mx = 1;
        for (int v = 0; v < U; v++) if (s_cnt[v] > mx) mx = s_cnt[v];
        int kq = (mx + KSPLIT - 1) / KSPLIT;
        s_Kpad = kq * KSPLIT;
        g_Kq   = kq;
    }
    __syncthreads();
    int Kpad = s_Kpad;

    float Cn = 0.f, Cd = 0.f;
    int k = 0;
    for (int j = 0; j < U; j++) {
        float m = mask[j*U + u];
        if (m != 0.f) {
            float sg = sigma[j*U + u];
            float wp = softplusf(w[j*U + u]) * m;
            float hw = 0.5f * wp * erev[j*U + u];    // |hw| = 0.5*wp
            float4 ent;
            ent.x = 0.5f * sg;
            ent.y = -0.5f * mu[j*U + u] * sg;
            ent.z = hw;
            ent.w = __int_as_float(j);
            g_synT[k*U + u] = ent;
            Cn += hw;
            Cd += 0.5f * wp;
            k++;
        }
    }
    g_Cn[u] = Cn;
    g_Cd[u] = Cd;
    // padding: zero weight, j=0 (contribution multiplied by 0)
    for (; k < Kpad; k++) {
        float4 z; z.x = 0.f; z.y = 0.f; z.z = 0.f; z.w = __int_as_float(0);
        g_synT[k*U + u] = z;
    }
}

// ---------------- sensory precompute: LayerNorm + sensory synapse sums -----
__global__ void sens_kernel(const float* __restrict__ x, const float* __restrict__ ln_g,
                            const float* __restrict__ ln_b, const float* __restrict__ in_w,
                            const float* __restrict__ in_b)
{
    int t = blockIdx.x;
    int b = blockIdx.y;
    int u = threadIdx.x;

    const float* xp = x + (b*TT + t)*NIN;
    float xv[NIN];
    float mean = 0.f;
    #pragma unroll
    for (int i = 0; i < NIN; i++) { xv[i] = xp[i]; mean += xv[i]; }
    mean *= (1.f/NIN);
    float var = 0.f;
    #pragma unroll
    for (int i = 0; i < NIN; i++) { float d = xv[i] - mean; var += d*d; }
    var *= (1.f/NIN);
    float inv = rsqrtf(var + 1e-5f);

    float inp[NIN];
    #pragma unroll
    for (int i = 0; i < NIN; i++)
        inp[i] = ((xv[i]-mean)*inv*ln_g[i] + ln_b[i]) * in_w[i] + in_b[i];

    float num = 0.f, den = 0.f;
    #pragma unroll
    for (int i = 0; i < NIN; i++) {
        float4 S = g_sensw[i*U + u];
        float e = fast_ex2(fmaf(inp[i], S.x, S.y));
        float r = fast_rcp(1.f + e);
        num = fmaf(S.w, r, num);
        den = fmaf(S.z, r, den);
    }
    // batch b -> group g = b>>3, half h = (b>>2)&1, slot s = b&3
    int g = b >> 3, h = (b >> 2) & 1, s = b & 3;
    int idx = ((((g*TT + t)*U + u)*2) + h)*4 + s;
    ((float*)g_snum)[idx] = num;
    ((float*)g_sden)[idx] = den;
}

// ---------------- main LTC recurrence: k-split x4, 8 batches, 512 threads --
__global__ void __launch_bounds__(512) ltc_main(const float* __restrict__ out_w,
                                                const float* __restrict__ out_b)
{
    __shared__ float4 vA[2][U];          // batches 0-3
    __shared__ float4 vB[2][U];          // batches 4-7
    __shared__ float4 s_part[U][17];     // [u][kh*4 + c], c: nA nB dA dB; 17 kills conflicts
    __shared__ float  s_ow[MOTOR], s_ob[MOTOR];

    int tid = threadIdx.x;
    int u  = tid & 127;
    int kh = tid >> 7;          // synapse quarter 0..3
    int g  = blockIdx.x;
    int Kq = g_Kq;

    float cmt = g_cmt[u], gl = g_gl[u], glv = g_glv[u];
    float Cn = g_Cn[u],   Cd = g_Cd[u];
    float dc = cmt + gl + Cd;
    float nc = glv + Cn;

    if (tid < MOTOR) { s_ow[tid] = out_w[tid]; s_ob[tid] = out_b[tid]; }
    if (kh == 0) {
        vA[0][u] = make_float4(0.f, 0.f, 0.f, 0.f);
        vB[0][u] = make_float4(0.f, 0.f, 0.f, 0.f);
    }
    __syncthreads();
    int cur = 0;

    const float4* __restrict__ syn  = g_synT + kh*Kq*U;
    const float4* __restrict__ snum = g_snum + g*TT*U*2;
    const float4* __restrict__ sden = g_sden + g*TT*U*2;

    int m  = u & 63;
    int h  = u >> 6;
    int b0 = g * 8;

    for (int t = 0; t < TT; t++) {
        // base terms (needed only by the kh==0 reducer warps; warp-uniform guard)
        float bn[8], bd[8];
        if (kh == 0) {
            float4 snA = snum[(t*U + u)*2 + 0];
            float4 snB = snum[(t*U + u)*2 + 1];
            float4 sdA = sden[(t*U + u)*2 + 0];
            float4 sdB = sden[(t*U + u)*2 + 1];
            bn[0]=nc+snA.x; bn[1]=nc+snA.y; bn[2]=nc+snA.z; bn[3]=nc+snA.w;
            bn[4]=nc+snB.x; bn[5]=nc+snB.y; bn[6]=nc+snB.z; bn[7]=nc+snB.w;
            bd[0]=dc+sdA.x; bd[1]=dc+sdA.y; bd[2]=dc+sdA.z; bd[3]=dc+sdA.w;
            bd[4]=dc+sdB.x; bd[5]=dc+sdB.y; bd[6]=dc+sdB.z; bd[7]=dc+sdB.w;
        }

        #pragma unroll 1
        for (int f = 0; f < NUNF; f++) {
            // --- compute phase: every thread does Kq branch-free iterations ---
            const float4* va = vA[cur];
            const float4* vb = vB[cur];
            float n0=0.f,n1=0.f,n2=0.f,n3=0.f,n4=0.f,n5=0.f,n6=0.f,n7=0.f;
            float d0=0.f,d1=0.f,d2=0.f,d3=0.f,d4=0.f,d5=0.f,d6=0.f,d7=0.f;
            #pragma unroll 2
            for (int k = 0; k < Kq; k++) {
                float4 W = __ldg(&syn[k*U + u]);
                int j = __float_as_int(W.w);
                float4 aJ = va[j];
                float4 bJ = vb[j];
                float hz = fabsf(W.z);
                float t0 = fast_tanh(fmaf(aJ.x, W.x, W.y));
                float t1 = fast_tanh(fmaf(aJ.y, W.x, W.y));
                float t2 = fast_tanh(fmaf(aJ.z, W.x, W.y));
                float t3 = fast_tanh(fmaf(aJ.w, W.x, W.y));
                float t4 = fast_tanh(fmaf(bJ.x, W.x, W.y));
                float t5 = fast_tanh(fmaf(bJ.y, W.x, W.y));
                float t6 = fast_tanh(fmaf(bJ.z, W.x, W.y));
                float t7 = fast_tanh(fmaf(bJ.w, W.x, W.y));
                n0 = fmaf(W.z, t0, n0); d0 = fmaf(hz, t0, d0);
                n1 = fmaf(W.z, t1, n1); d1 = fmaf(hz, t1, d1);
                n2 = fmaf(W.z, t2, n2); d2 = fmaf(hz, t2, d2);
                n3 = fmaf(W.z, t3, n3); d3 = fmaf(hz, t3, d3);
                n4 = fmaf(W.z, t4, n4); d4 = fmaf(hz, t4, d4);
                n5 = fmaf(W.z, t5, n5); d5 = fmaf(hz, t5, d5);
                n6 = fmaf(W.z, t6, n6); d6 = fmaf(hz, t6, d6);
                n7 = fmaf(W.z, t7, n7); d7 = fmaf(hz, t7, d7);
            }
            s_part[u][kh*4 + 0] = make_float4(n0, n1, n2, n3);
            s_part[u][kh*4 + 1] = make_float4(n4, n5, n6, n7);
            s_part[u][kh*4 + 2] = make_float4(d0, d1, d2, d3);
            s_part[u][kh*4 + 3] = make_float4(d4, d5, d6, d7);
            __syncthreads();

            // --- reduce phase: kh==0 warps combine 4 partials, update v ---
            if (kh == 0) {
                float4 vuA = vA[cur][u];
                float4 vuB = vB[cur][u];
                float N0 = fmaf(cmt, vuA.x, bn[0]);
                float N1 = fmaf(cmt, vuA.y, bn[1]);
                float N2 = fmaf(cmt, vuA.z, bn[2]);
                float N3 = fmaf(cmt, vuA.w, bn[3]);
                float N4 = fmaf(cmt, vuB.x, bn[4]);
                float N5 = fmaf(cmt, vuB.y, bn[5]);
                float N6 = fmaf(cmt, vuB.z, bn[6]);
                float N7 = fmaf(cmt, vuB.w, bn[7]);
                float D0=bd[0],D1=bd[1],D2=bd[2],D3=bd[3];
                float D4=bd[4],D5=bd[5],D6=bd[6],D7=bd[7];
                #pragma unroll
                for (int p = 0; p < KSPLIT; p++) {
                    float4 a = s_part[u][p*4 + 0];
                    float4 b = s_part[u][p*4 + 1];
                    float4 c = s_part[u][p*4 + 2];
                    float4 d = s_part[u][p*4 + 3];
                    N0 += a.x; N1 += a.y; N2 += a.z; N3 += a.w;
                    N4 += b.x; N5 += b.y; N6 += b.z; N7 += b.w;
                    D0 += c.x; D1 += c.y; D2 += c.z; D3 += c.w;
                    D4 += d.x; D5 += d.y; D6 += d.z; D7 += d.w;
                }
                float4 wAo, wBo;
                wAo.x = N0 * fast_rcp(D0 + EPSF);
                wAo.y = N1 * fast_rcp(D1 + EPSF);
                wAo.z = N2 * fast_rcp(D2 + EPSF);
                wAo.w = N3 * fast_rcp(D3 + EPSF);
                wBo.x = N4 * fast_rcp(D4 + EPSF);
                wBo.y = N5 * fast_rcp(D5 + EPSF);
                wBo.z = N6 * fast_rcp(D6 + EPSF);
                wBo.w = N7 * fast_rcp(D7 + EPSF);
                vA[cur ^ 1][u] = wAo;
                vB[cur ^ 1][u] = wBo;
            }
            __syncthreads();
            cur ^= 1;
        }

        // coalesced motor-output write (kh==0 warps; vA/vB[cur] stable until
        // next unfold's reduce phase, which is after a barrier)
        if (kh == 0) {
            float4 vv = (h == 0) ? vA[cur][m] : vB[cur][m];
            float ww = s_ow[m], bb = s_ob[m];
            g_outs[((b0 + 4*h + 0)*TT + t)*MOTOR + m] = fmaf(vv.x, ww, bb);
            g_outs[((b0 + 4*h + 1)*TT + t)*MOTOR + m] = fmaf(vv.y, ww, bb);
            g_outs[((b0 + 4*h + 2)*TT + t)*MOTOR + m] = fmaf(vv.z, ww, bb);
            g_outs[((b0 + 4*h + 3)*TT + t)*MOTOR + m] = fmaf(vv.w, ww, bb);
        }
    }
}

// ---------------- attention pooling + classifier ----------------------------
__global__ void __launch_bounds__(128) attn_kernel(
    const float* __restrict__ aw1, const float* __restrict__ ab1,
    const float* __restrict__ aw2, const float* __restrict__ cw1,
    const float* __restrict__ cb1, const float* __restrict__ cw2,
    const float* __restrict__ cb2, float* __restrict__ out)
{
    __shared__ float so[TT][MOTOR+1];
    __shared__ float w1[MOTOR*32];
    __shared__ float sc[TT];
    __shared__ float ctx[MOTOR];
    __shared__ float hid[128];

    int b = blockIdx.x, tid = threadIdx.x;

    for (int i = tid; i < TT*MOTOR; i += 128)
        so[i/MOTOR][i%MOTOR] = g_outs[b*TT*MOTOR + i];
    for (int i = tid; i < MOTOR*32; i += 128)
        w1[i] = aw1[i];
    __syncthreads();

    if (tid < TT) {
        float acc = 0.f;
        for (int hh = 0; hh < 32; hh++) {
            float s = ab1[hh];
            #pragma unroll 8
            for (int uu = 0; uu < MOTOR; uu++)
                s = fmaf(so[tid][uu], w1[uu*32 + hh], s);
            s = fmaxf(s, 0.f);
            acc = fmaf(s, aw2[hh], acc);
        }
        sc[tid] = acc;
    }
    __syncthreads();

    if (tid == 0) {
        float mm = -1e30f;
        for (int t = 0; t < TT; t++) mm = fmaxf(mm, sc[t]);
        float s = 0.f;
        for (int t = 0; t < TT; t++) { float e = __expf(sc[t]-mm); sc[t] = e; s += e; }
        float invs = 1.f / s;
        for (int t = 0; t < TT; t++) sc[t] *= invs;
    }
    __syncthreads();

    if (tid < MOTOR) {
        float a = 0.f;
        for (int t = 0; t < TT; t++) a = fmaf(sc[t], so[t][tid], a);
        ctx[tid] = a;
    }
    __syncthreads();

    {
        float s = cb1[tid];
        for (int uu = 0; uu < MOTOR; uu++)
            s = fmaf(ctx[uu], cw1[uu*128 + tid], s);
        hid[tid] = fmaxf(s, 0.f);
    }
    __syncthreads();

    if (tid < NCLS) {
        float s = cb2[tid];
        for (int hh = 0; hh < 128; hh++)
            s = fmaf(hid[hh], cw2[hh*NCLS + tid], s);
        out[b*NCLS + tid] = s;
    }
}

// ---------------- launch ----------------------------------------------------
extern "C" void kernel_launch(void* const* d_in, const int* in_sizes, int n_in,
                              void* d_out, int out_size)
{
    const float* x        = (const float*)d_in[0];
    const float* ln_g     = (const float*)d_in[1];
    const float* ln_b     = (const float*)d_in[2];
    const float* gleak    = (const float*)d_in[3];
    const float* vleak    = (const float*)d_in[4];
    const float* cm       = (const float*)d_in[5];
    const float* sigma    = (const float*)d_in[6];
    const float* mu       = (const float*)d_in[7];
    const float* w        = (const float*)d_in[8];
    const float* erev     = (const float*)d_in[9];
    const float* ssig     = (const float*)d_in[10];
    const float* smu      = (const float*)d_in[11];
    const float* sw       = (const float*)d_in[12];
    const float* serev    = (const float*)d_in[13];
    const float* in_w     = (const float*)d_in[14];
    const float* in_b     = (const float*)d_in[15];
    const float* out_w    = (const float*)d_in[16];
    const float* out_b    = (const float*)d_in[17];
    const float* aw1      = (const float*)d_in[18];
    const float* ab1      = (const float*)d_in[19];
    const float* aw2      = (const float*)d_in[20];
    const float* cw1      = (const float*)d_in[21];
    const float* cb1      = (const float*)d_in[22];
    const float* cw2      = (const float*)d_in[23];
    const float* cb2      = (const float*)d_in[24];
    const float* mask     = (const float*)d_in[25];
    const float* smask    = (const float*)d_in[26];

    prep_kernel<<<1, U>>>(gleak, vleak, cm, sigma, mu, w, erev,
                          ssig, smu, sw, serev, mask, smask);
    sens_kernel<<<dim3(TT, BATCH), U>>>(x, ln_g, ln_b, in_w, in_b);
    ltc_main<<<NG8, 512>>>(out_w, out_b);
    attn_kernel<<<BATCH, 128>>>(aw1, ab1, aw2, cw1, cb1, cw2, cb2, (float*)d_out);
}

// round 9
// speedup vs baseline: 1.7681x; 1.0270x over previous
#include <cuda_runtime.h>
#include <cuda_bf16.h>

#define U      128
#define TT     96
#define NIN    6
#define NUNF   6
#define MOTOR  64
#define NCLS   100
#define BATCH  1024
#define NG8    (BATCH/8)
#define LOG2E  1.4426950408889634f
#define EPSF   1e-8f
#define KSPLIT 4

// ---------------- scratch (device globals; no allocation allowed) ----------
// Count-sorted slots + kh-sliced tables, exact per-thread bounds (no padding).
// Entry l of slot s -> slice kh=l&3, idx i=l>>2, stored at
// g_synT[(kh*KQMAX + i)*U + s] = (A=0.5*sigma, B=-0.5*mu*sigma,
//                                 hw=0.5*wp*erev, bitcast int j_slot)
__device__ float4 g_synT[U*U];
__device__ int    g_KQmax;                // = ceil(maxcnt/KSPLIT)
__device__ int    g_scnt[U];              // per-slot synapse count
__device__ int    g_inv[U];               // unit -> slot
__device__ float  g_cmt[U], g_gl[U], g_glv[U];   // per-slot
__device__ float  g_Cn[U], g_Cd[U];       // per-slot constant half-sums
__device__ float4 g_sensw[NIN*U];         // sensory (A,B,swp,swp*erev), unit-indexed
__device__ float4 g_snum[NG8*TT*U*2];     // [g][t][slot][h] float4 = 4 batches
__device__ float4 g_sden[NG8*TT*U*2];
__device__ float  g_outs[BATCH*TT*MOTOR];

__device__ __forceinline__ float fast_ex2(float x){ float y; asm("ex2.approx.ftz.f32 %0, %1;" : "=f"(y) : "f"(x)); return y; }
__device__ __forceinline__ float fast_rcp(float x){ float y; asm("rcp.approx.ftz.f32 %0, %1;" : "=f"(y) : "f"(x)); return y; }
__device__ __forceinline__ float fast_tanh(float x){ float y; asm("tanh.approx.f32 %0, %1;" : "=f"(y) : "f"(x)); return y; }
__device__ __forceinline__ float softplusf(float x){ return (x > 20.f) ? x : log1pf(expf(x)); }

// ---------------- prep: sort by count + exact sliced tables ----------------
__global__ void prep_kernel(const float* gleak, const float* vleak, const float* cm,
                            const float* sigma, const float* mu, const float* w,
                            const float* erev, const float* ss, const float* smu,
                            const float* sw, const float* serev,
                            const float* mask, const float* smask)
{
    __shared__ int s_cnt[U];
    __shared__ int s_inv[U];
    __shared__ int s_KQ;
    int u = threadIdx.x;

    // sensory weights (ex2 form, unit-indexed)
    for (int i = 0; i < NIN; i++) {
        float m  = smask[i*U + u];
        float sg = ss[i*U + u];
        float wp = softplusf(sw[i*U + u]) * m;
        float4 e;
        e.x = -sg * LOG2E;
        e.y = smu[i*U + u] * sg * LOG2E;
        e.z = wp;
        e.w = wp * serev[i*U + u];
        g_sensw[i*U + u] = e;
    }

    int cnt = 0;
    for (int j = 0; j < U; j++)
        if (mask[j*U + u] != 0.f) cnt++;
    s_cnt[u] = cnt;
    __syncthreads();

    // stable rank by (cnt, u) ascending -> slot
    int r = 0;
    for (int v = 0; v < U; v++) {
        int c = s_cnt[v];
        if (c < cnt || (c == cnt && v < u)) r++;
    }
    s_inv[u] = r;
    __syncthreads();

    if (u == 0) {
        int mx = 1;
        for (int v = 0; v < U; v++) if (s_cnt[v] > mx) mx = s_cnt[v];
        int kq = (mx + KSPLIT - 1) / KSPLIT;
        s_KQ = kq;
        g_KQmax = kq;
    }
    __syncthreads();
    int KQMAX = s_KQ;

    g_inv[u]  = r;
    g_scnt[r] = cnt;
    g_cmt[r]  = softplusf(cm[u]) * (float)NUNF;
    float gl  = softplusf(gleak[u]);
    g_gl[r]   = gl;
    g_glv[r]  = gl * vleak[u];

    float Cn = 0.f, Cd = 0.f;
    int l = 0;
    for (int j = 0; j < U; j++) {
        float m = mask[j*U + u];
        if (m != 0.f) {
            float sg = sigma[j*U + u];
            float wp = softplusf(w[j*U + u]) * m;
            float hw = 0.5f * wp * erev[j*U + u];    // |hw| = 0.5*wp
            int kh = l & 3, i = l >> 2;
            float4 ent;
            ent.x = 0.5f * sg;
            ent.y = -0.5f * mu[j*U + u] * sg;
            ent.z = hw;
            ent.w = __int_as_float(s_inv[j]);        // source slot
            g_synT[(kh*KQMAX + i)*U + r] = ent;
            Cn += hw;
            Cd += 0.5f * wp;
            l++;
        }
    }
    g_Cn[r] = Cn;
    g_Cd[r] = Cd;
}

// ---------------- sensory: LayerNorm + sensory sums, ltc-native layout -----
__global__ void __launch_bounds__(U) sens_kernel(
    const float* __restrict__ x, const float* __restrict__ ln_g,
    const float* __restrict__ ln_b, const float* __restrict__ in_w,
    const float* __restrict__ in_b)
{
    int t = blockIdx.x;
    int g = blockIdx.y;
    int u = threadIdx.x;

    float nq[8], dq[8];
    #pragma unroll
    for (int q = 0; q < 8; q++) {
        int b = g*8 + q;
        const float* xp = x + (b*TT + t)*NIN;
        float xv[NIN];
        float mean = 0.f;
        #pragma unroll
        for (int i = 0; i < NIN; i++) { xv[i] = xp[i]; mean += xv[i]; }
        mean *= (1.f/NIN);
        float var = 0.f;
        #pragma unroll
        for (int i = 0; i < NIN; i++) { float d = xv[i] - mean; var += d*d; }
        var *= (1.f/NIN);
        float inv = rsqrtf(var + 1e-5f);

        float num = 0.f, den = 0.f;
        #pragma unroll
        for (int i = 0; i < NIN; i++) {
            float inp = ((xv[i]-mean)*inv*ln_g[i] + ln_b[i]) * in_w[i] + in_b[i];
            float4 S = g_sensw[i*U + u];
            float e = fast_ex2(fmaf(inp, S.x, S.y));
            float rr = fast_rcp(1.f + e);
            num = fmaf(S.w, rr, num);
            den = fmaf(S.z, rr, den);
        }
        nq[q] = num; dq[q] = den;
    }

    int slot = g_inv[u];
    int base = ((g*TT + t)*U + slot)*2;
    g_snum[base + 0] = make_float4(nq[0], nq[1], nq[2], nq[3]);
    g_snum[base + 1] = make_float4(nq[4], nq[5], nq[6], nq[7]);
    g_sden[base + 0] = make_float4(dq[0], dq[1], dq[2], dq[3]);
    g_sden[base + 1] = make_float4(dq[4], dq[5], dq[6], dq[7]);
}

// ---------------- main LTC recurrence: sorted, exact bounds, k-split x4 ----
__global__ void __launch_bounds__(512) ltc_main(const float* __restrict__ out_w,
                                                const float* __restrict__ out_b)
{
    __shared__ float4 vA[2][U];          // batches 0-3 (slot-indexed)
    __shared__ float4 vB[2][U];          // batches 4-7
    __shared__ float4 s_part[U][17];     // [slot][kh*4+c]; 17 kills conflicts
    __shared__ float  s_ow[MOTOR], s_ob[MOTOR];
    __shared__ int    s_mslot[MOTOR];

    int tid = threadIdx.x;
    int u  = tid & 127;                  // slot
    int kh = tid >> 7;                   // synapse slice 0..3
    int g  = blockIdx.x;
    int KQMAX = g_KQmax;
    int cnt = g_scnt[u];
    int myK = (cnt + 3 - kh) >> 2;       // exact per-thread bound

    float cmt = g_cmt[u], gl = g_gl[u], glv = g_glv[u];
    float Cn = g_Cn[u],   Cd = g_Cd[u];
    float dc = cmt + gl + Cd;
    float nc = glv + Cn;

    if (tid < MOTOR) {
        s_ow[tid] = out_w[tid];
        s_ob[tid] = out_b[tid];
        s_mslot[tid] = g_inv[tid];
    }
    if (kh == 0) {
        vA[0][u] = make_float4(0.f, 0.f, 0.f, 0.f);
        vB[0][u] = make_float4(0.f, 0.f, 0.f, 0.f);
    }
    __syncthreads();
    int cur = 0;

    const float4* __restrict__ syn  = g_synT + kh*KQMAX*U;
    const float4* __restrict__ snum = g_snum + g*TT*U*2;
    const float4* __restrict__ sden = g_sden + g*TT*U*2;

    int m  = u & 63;
    int h  = u >> 6;
    int b0 = g * 8;

    for (int t = 0; t < TT; t++) {
        float bn[8], bd[8];
        if (kh == 0) {
            float4 snA = snum[(t*U + u)*2 + 0];
            float4 snB = snum[(t*U + u)*2 + 1];
            float4 sdA = sden[(t*U + u)*2 + 0];
            float4 sdB = sden[(t*U + u)*2 + 1];
            bn[0]=nc+snA.x; bn[1]=nc+snA.y; bn[2]=nc+snA.z; bn[3]=nc+snA.w;
            bn[4]=nc+snB.x; bn[5]=nc+snB.y; bn[6]=nc+snB.z; bn[7]=nc+snB.w;
            bd[0]=dc+sdA.x; bd[1]=dc+sdA.y; bd[2]=dc+sdA.z; bd[3]=dc+sdA.w;
            bd[4]=dc+sdB.x; bd[5]=dc+sdB.y; bd[6]=dc+sdB.z; bd[7]=dc+sdB.w;
        }

        #pragma unroll 1
        for (int f = 0; f < NUNF; f++) {
            // --- compute phase: exact myK iterations, branch-free body ---
            const float4* va = vA[cur];
            const float4* vb = vB[cur];
            float n0=0.f,n1=0.f,n2=0.f,n3=0.f,n4=0.f,n5=0.f,n6=0.f,n7=0.f;
            float d0=0.f,d1=0.f,d2=0.f,d3=0.f,d4=0.f,d5=0.f,d6=0.f,d7=0.f;
            #pragma unroll 2
            for (int k = 0; k < myK; k++) {
                float4 W = __ldg(&syn[k*U + u]);
                int j = __float_as_int(W.w);
                float4 aJ = va[j];
                float4 bJ = vb[j];
                float hz = fabsf(W.z);
                float t0 = fast_tanh(fmaf(aJ.x, W.x, W.y));
                float t1 = fast_tanh(fmaf(aJ.y, W.x, W.y));
                float t2 = fast_tanh(fmaf(aJ.z, W.x, W.y));
                float t3 = fast_tanh(fmaf(aJ.w, W.x, W.y));
                float t4 = fast_tanh(fmaf(bJ.x, W.x, W.y));
                float t5 = fast_tanh(fmaf(bJ.y, W.x, W.y));
                float t6 = fast_tanh(fmaf(bJ.z, W.x, W.y));
                float t7 = fast_tanh(fmaf(bJ.w, W.x, W.y));
                n0 = fmaf(W.z, t0, n0); d0 = fmaf(hz, t0, d0);
                n1 = fmaf(W.z, t1, n1); d1 = fmaf(hz, t1, d1);
                n2 = fmaf(W.z, t2, n2); d2 = fmaf(hz, t2, d2);
                n3 = fmaf(W.z, t3, n3); d3 = fmaf(hz, t3, d3);
                n4 = fmaf(W.z, t4, n4); d4 = fmaf(hz, t4, d4);
                n5 = fmaf(W.z, t5, n5); d5 = fmaf(hz, t5, d5);
                n6 = fmaf(W.z, t6, n6); d6 = fmaf(hz, t6, d6);
                n7 = fmaf(W.z, t7, n7); d7 = fmaf(hz, t7, d7);
            }
            s_part[u][kh*4 + 0] = make_float4(n0, n1, n2, n3);
            s_part[u][kh*4 + 1] = make_float4(n4, n5, n6, n7);
            s_part[u][kh*4 + 2] = make_float4(d0, d1, d2, d3);
            s_part[u][kh*4 + 3] = make_float4(d4, d5, d6, d7);
            __syncthreads();

            // --- reduce phase: kh==0 warps combine 4 partials, update v ---
            if (kh == 0) {
                float4 vuA = vA[cur][u];
                float4 vuB = vB[cur][u];
                float N0 = fmaf(cmt, vuA.x, bn[0]);
                float N1 = fmaf(cmt, vuA.y, bn[1]);
                float N2 = fmaf(cmt, vuA.z, bn[2]);
                float N3 = fmaf(cmt, vuA.w, bn[3]);
                float N4 = fmaf(cmt, vuB.x, bn[4]);
                float N5 = fmaf(cmt, vuB.y, bn[5]);
                float N6 = fmaf(cmt, vuB.z, bn[6]);
                float N7 = fmaf(cmt, vuB.w, bn[7]);
                float D0=bd[0],D1=bd[1],D2=bd[2],D3=bd[3];
                float D4=bd[4],D5=bd[5],D6=bd[6],D7=bd[7];
                #pragma unroll
                for (int p = 0; p < KSPLIT; p++) {
                    float4 a = s_part[u][p*4 + 0];
                    float4 b = s_part[u][p*4 + 1];
                    float4 c = s_part[u][p*4 + 2];
                    float4 d = s_part[u][p*4 + 3];
                    N0 += a.x; N1 += a.y; N2 += a.z; N3 += a.w;
                    N4 += b.x; N5 += b.y; N6 += b.z; N7 += b.w;
                    D0 += c.x; D1 += c.y; D2 += c.z; D3 += c.w;
                    D4 += d.x; D5 += d.y; D6 += d.z; D7 += d.w;
                }
                float4 wAo, wBo;
                wAo.x = N0 * fast_rcp(D0 + EPSF);
                wAo.y = N1 * fast_rcp(D1 + EPSF);
                wAo.z = N2 * fast_rcp(D2 + EPSF);
                wAo.w = N3 * fast_rcp(D3 + EPSF);
                wBo.x = N4 * fast_rcp(D4 + EPSF);
                wBo.y = N5 * fast_rcp(D5 + EPSF);
                wBo.z = N6 * fast_rcp(D6 + EPSF);
                wBo.w = N7 * fast_rcp(D7 + EPSF);
                vA[cur ^ 1][u] = wAo;
                vB[cur ^ 1][u] = wBo;
            }
            __syncthreads();
            cur ^= 1;
        }

        // coalesced motor-output write (kh==0 warps; gather through slot map)
        if (kh == 0) {
            int ms = s_mslot[m];
            float4 vv = (h == 0) ? vA[cur][ms] : vB[cur][ms];
            float ww = s_ow[m], bb = s_ob[m];
            g_outs[((b0 + 4*h + 0)*TT + t)*MOTOR + m] = fmaf(vv.x, ww, bb);
            g_outs[((b0 + 4*h + 1)*TT + t)*MOTOR + m] = fmaf(vv.y, ww, bb);
            g_outs[((b0 + 4*h + 2)*TT + t)*MOTOR + m] = fmaf(vv.z, ww, bb);
            g_outs[((b0 + 4*h + 3)*TT + t)*MOTOR + m] = fmaf(vv.w, ww, bb);
        }
    }
}

// ---------------- attention pooling + classifier ----------------------------
__global__ void __launch_bounds__(128) attn_kernel(
    const float* __restrict__ aw1, const float* __restrict__ ab1,
    const float* __restrict__ aw2, const float* __restrict__ cw1,
    const float* __restrict__ cb1, const float* __restrict__ cw2,
    const float* __restrict__ cb2, float* __restrict__ out)
{
    __shared__ float so[TT][MOTOR+1];
    __shared__ float w1[MOTOR*32];
    __shared__ float sc[TT];
    __shared__ float ctx[MOTOR];
    __shared__ float hid[128];

    int b = blockIdx.x, tid = threadIdx.x;

    for (int i = tid; i < TT*MOTOR; i += 128)
        so[i/MOTOR][i%MOTOR] = g_outs[b*TT*MOTOR + i];
    for (int i = tid; i < MOTOR*32; i += 128)
        w1[i] = aw1[i];
    __syncthreads();

    if (tid < TT) {
        float acc = 0.f;
        for (int hh = 0; hh < 32; hh++) {
            float s = ab1[hh];
            #pragma unroll 8
            for (int uu = 0; uu < MOTOR; uu++)
                s = fmaf(so[tid][uu], w1[uu*32 + hh], s);
            s = fmaxf(s, 0.f);
            acc = fmaf(s, aw2[hh], acc);
        }
        sc[tid] = acc;
    }
    __syncthreads();

    if (tid == 0) {
        float mm = -1e30f;
        for (int t = 0; t < TT; t++) mm = fmaxf(mm, sc[t]);
        float s = 0.f;
        for (int t = 0; t < TT; t++) { float e = __expf(sc[t]-mm); sc[t] = e; s += e; }
        float invs = 1.f / s;
        for (int t = 0; t < TT; t++) sc[t] *= invs;
    }
    __syncthreads();

    if (tid < MOTOR) {
        float a = 0.f;
        for (int t = 0; t < TT; t++) a = fmaf(sc[t], so[t][tid], a);
        ctx[tid] = a;
    }
    __syncthreads();

    {
        float s = cb1[tid];
        for (int uu = 0; uu < MOTOR; uu++)
            s = fmaf(ctx[uu], cw1[uu*128 + tid], s);
        hid[tid] = fmaxf(s, 0.f);
    }
    __syncthreads();

    if (tid < NCLS) {
        float s = cb2[tid];
        for (int hh = 0; hh < 128; hh++)
            s = fmaf(hid[hh], cw2[hh*NCLS + tid], s);
        out[b*NCLS + tid] = s;
    }
}

// ---------------- launch ----------------------------------------------------
extern "C" void kernel_launch(void* const* d_in, const int* in_sizes, int n_in,
                              void* d_out, int out_size)
{
    const float* x        = (const float*)d_in[0];
    const float* ln_g     = (const float*)d_in[1];
    const float* ln_b     = (const float*)d_in[2];
    const float* gleak    = (const float*)d_in[3];
    const float* vleak    = (const float*)d_in[4];
    const float* cm       = (const float*)d_in[5];
    const float* sigma    = (const float*)d_in[6];
    const float* mu       = (const float*)d_in[7];
    const float* w        = (const float*)d_in[8];
    const float* erev     = (const float*)d_in[9];
    const float* ssig     = (const float*)d_in[10];
    const float* smu      = (const float*)d_in[11];
    const float* sw       = (const float*)d_in[12];
    const float* serev    = (const float*)d_in[13];
    const float* in_w     = (const float*)d_in[14];
    const float* in_b     = (const float*)d_in[15];
    const float* out_w    = (const float*)d_in[16];
    const float* out_b    = (const float*)d_in[17];
    const float* aw1      = (const float*)d_in[18];
    const float* ab1      = (const float*)d_in[19];
    const float* aw2      = (const float*)d_in[20];
    const float* cw1      = (const float*)d_in[21];
    const float* cb1      = (const float*)d_in[22];
    const float* cw2      = (const float*)d_in[23];
    const float* cb2      = (const float*)d_in[24];
    const float* mask     = (const float*)d_in[25];
    const float* smask    = (const float*)d_in[26];

    prep_kernel<<<1, U>>>(gleak, vleak, cm, sigma, mu, w, erev,
                          ssig, smu, sw, serev, mask, smask);
    sens_kernel<<<dim3(TT, NG8), U>>>(x, ln_g, ln_b, in_w, in_b);
    ltc_main<<<NG8, 512>>>(out_w, out_b);
    attn_kernel<<<BATCH, 128>>>(aw1, ab1, aw2, cw1, cb1, cw2, cb2, (float*)d_out);
}

// round 11
// speedup vs baseline: 1.8725x; 1.0591x over previous
#include <cuda_runtime.h>
#include <cuda_bf16.h>

#define U      128
#define TT     96
#define NIN    6
#define NUNF   6
#define MOTOR  64
#define NCLS   100
#define BATCH  1024
#define NG8    (BATCH/8)
#define LOG2E  1.4426950408889634f
#define EPSF   1e-8f
#define KSPLIT 4

// ---------------- scratch (device globals; no allocation allowed) ----------
// Count-sorted slots + kh-sliced tables, exact per-thread bounds (no padding).
// Entry l of slot s -> slice kh=l&3, idx i=l>>2, stored at
// g_synT[(kh*KQMAX + i)*U + s] = (A=0.5*sigma, B=-0.5*mu*sigma,
//                                 hw=0.5*wp*erev, bitcast int j_slot)
__device__ float4 g_synT[U*U];
__device__ int    g_KQmax;                // = ceil(maxcnt/KSPLIT)
__device__ int    g_scnt[U];              // per-slot synapse count
__device__ int    g_inv[U];               // unit -> slot
__device__ float  g_cmt[U], g_gl[U], g_glv[U];   // per-slot
__device__ float  g_Cn[U], g_Cd[U];       // per-slot constant half-sums
__device__ float4 g_sensw[NIN*U];         // sensory (A,B,swp,swp*erev), ex2 form
__device__ float4 g_snum[NG8*TT*U*2];     // [g][t][slot][h] float4 = 4 batches
__device__ float4 g_sden[NG8*TT*U*2];
__device__ float  g_outs[BATCH*TT*MOTOR];

__device__ __forceinline__ float fast_ex2(float x){ float y; asm("ex2.approx.ftz.f32 %0, %1;" : "=f"(y) : "f"(x)); return y; }
__device__ __forceinline__ float fast_rcp(float x){ float y; asm("rcp.approx.ftz.f32 %0, %1;" : "=f"(y) : "f"(x)); return y; }
__device__ __forceinline__ float fast_tanh(float x){ float y; asm("tanh.approx.f32 %0, %1;" : "=f"(y) : "f"(x)); return y; }
__device__ __forceinline__ float softplusf(float x){ return (x > 20.f) ? x : log1pf(expf(x)); }

// ---------------- prep: sort by count + exact sliced tables ----------------
__global__ void prep_kernel(const float* gleak, const float* vleak, const float* cm,
                            const float* sigma, const float* mu, const float* w,
                            const float* erev, const float* ss, const float* smu,
                            const float* sw, const float* serev,
                            const float* mask, const float* smask)
{
    __shared__ int s_cnt[U];
    __shared__ int s_inv[U];
    __shared__ int s_KQ;
    int u = threadIdx.x;

    // sensory weights (ex2 form, unit-indexed)
    for (int i = 0; i < NIN; i++) {
        float m  = smask[i*U + u];
        float sg = ss[i*U + u];
        float wp = softplusf(sw[i*U + u]) * m;
        float4 e;
        e.x = -sg * LOG2E;
        e.y = smu[i*U + u] * sg * LOG2E;
        e.z = wp;
        e.w = wp * serev[i*U + u];
        g_sensw[i*U + u] = e;
    }

    int cnt = 0;
    for (int j = 0; j < U; j++)
        if (mask[j*U + u] != 0.f) cnt++;
    s_cnt[u] = cnt;
    __syncthreads();

    // stable rank by (cnt, u) ascending -> slot
    int r = 0;
    for (int v = 0; v < U; v++) {
        int c = s_cnt[v];
        if (c < cnt || (c == cnt && v < u)) r++;
    }
    s_inv[u] = r;
    __syncthreads();

    if (u == 0) {
        int mx = 1;
        for (int v = 0; v < U; v++) if (s_cnt[v] > mx) mx = s_cnt[v];
        int kq = (mx + KSPLIT - 1) / KSPLIT;
        s_KQ = kq;
        g_KQmax = kq;
    }
    __syncthreads();
    int KQMAX = s_KQ;

    g_inv[u]  = r;
    g_scnt[r] = cnt;
    g_cmt[r]  = softplusf(cm[u]) * (float)NUNF;
    float gl  = softplusf(gleak[u]);
    g_gl[r]   = gl;
    g_glv[r]  = gl * vleak[u];

    float Cn = 0.f, Cd = 0.f;
    int l = 0;
    for (int j = 0; j < U; j++) {
        float m = mask[j*U + u];
        if (m != 0.f) {
            float sg = sigma[j*U + u];
            float wp = softplusf(w[j*U + u]) * m;
            float hw = 0.5f * wp * erev[j*U + u];    // |hw| = 0.5*wp
            int kh = l & 3, i = l >> 2;
            float4 ent;
            ent.x = 0.5f * sg;
            ent.y = -0.5f * mu[j*U + u] * sg;
            ent.z = hw;
            ent.w = __int_as_float(s_inv[j]);        // source slot
            g_synT[(kh*KQMAX + i)*U + r] = ent;
            Cn += hw;
            Cd += 0.5f * wp;
            l++;
        }
    }
    g_Cn[r] = Cn;
    g_Cd[r] = Cd;
}

// ---------------- sensory: LayerNorm + sensory sums, ltc-native layout -----
__global__ void __launch_bounds__(U) sens_kernel(
    const float* __restrict__ x, const float* __restrict__ ln_g,
    const float* __restrict__ ln_b, const float* __restrict__ in_w,
    const float* __restrict__ in_b)
{
    int t = blockIdx.x;
    int g = blockIdx.y;
    int u = threadIdx.x;

    float nq[8], dq[8];
    #pragma unroll
    for (int q = 0; q < 8; q++) {
        int b = g*8 + q;
        const float* xp = x + (b*TT + t)*NIN;
        float xv[NIN];
        float mean = 0.f;
        #pragma unroll
        for (int i = 0; i < NIN; i++) { xv[i] = xp[i]; mean += xv[i]; }
        mean *= (1.f/NIN);
        float var = 0.f;
        #pragma unroll
        for (int i = 0; i < NIN; i++) { float d = xv[i] - mean; var += d*d; }
        var *= (1.f/NIN);
        float inv = rsqrtf(var + 1e-5f);

        float num = 0.f, den = 0.f;
        #pragma unroll
        for (int i = 0; i < NIN; i++) {
            float inp = ((xv[i]-mean)*inv*ln_g[i] + ln_b[i]) * in_w[i] + in_b[i];
            float4 S = g_sensw[i*U + u];
            float e = fast_ex2(fmaf(inp, S.x, S.y));
            float rr = fast_rcp(1.f + e);
            num = fmaf(S.w, rr, num);
            den = fmaf(S.z, rr, den);
        }
        nq[q] = num; dq[q] = den;
    }

    int slot = g_inv[u];
    int base = ((g*TT + t)*U + slot)*2;
    g_snum[base + 0] = make_float4(nq[0], nq[1], nq[2], nq[3]);
    g_snum[base + 1] = make_float4(nq[4], nq[5], nq[6], nq[7]);
    g_sden[base + 0] = make_float4(dq[0], dq[1], dq[2], dq[3]);
    g_sden[base + 1] = make_float4(dq[4], dq[5], dq[6], dq[7]);
}

// ---------------- main LTC recurrence: SMSP-balanced k-split ---------------
// Thread map: warp w = tid>>5; kh = w&3 (=> SMSP id), u-block = w>>2.
// Each SMSP processes one kh-slice of ALL u-blocks -> per-SMSP MUFU work is
// identical by construction. Reducer warps {kh==ublock} = SMSPs 0,1,2,3.
__global__ void __launch_bounds__(512) ltc_main(const float* __restrict__ out_w,
                                                const float* __restrict__ out_b)
{
    __shared__ float4 vA[2][U];          // batches 0-3 (slot-indexed)
    __shared__ float4 vB[2][U];          // batches 4-7
    __shared__ float4 s_part[U][17];     // [slot][kh*4+c]; 17 kills conflicts
    __shared__ float  s_ow[MOTOR], s_ob[MOTOR];
    __shared__ int    s_mslot[MOTOR];

    int tid  = threadIdx.x;
    int lane = tid & 31;
    int wrp  = tid >> 5;                 // 0..15
    int kh   = wrp & 3;                  // slice id == SMSP id
    int ub   = wrp >> 2;                 // u-block 0..3
    int u    = ub*32 + lane;             // slot
    bool red = (kh == ub);               // reducer warps: SMSPs 0..3, u covers all
    int g  = blockIdx.x;
    int KQMAX = g_KQmax;
    int cnt = g_scnt[u];
    int myK = (cnt + 3 - kh) >> 2;       // exact per-thread bound

    float cmt = g_cmt[u], gl = g_gl[u], glv = g_glv[u];
    float Cn = g_Cn[u],   Cd = g_Cd[u];
    float dc = cmt + gl + Cd;
    float nc = glv + Cn;

    if (tid < MOTOR) {
        s_ow[tid] = out_w[tid];
        s_ob[tid] = out_b[tid];
        s_mslot[tid] = g_inv[tid];
    }
    if (red) {
        vA[0][u] = make_float4(0.f, 0.f, 0.f, 0.f);
        vB[0][u] = make_float4(0.f, 0.f, 0.f, 0.f);
    }
    __syncthreads();
    int cur = 0;

    const float4* __restrict__ syn  = g_synT + kh*KQMAX*U;
    const float4* __restrict__ snum = g_snum + g*TT*U*2;
    const float4* __restrict__ sden = g_sden + g*TT*U*2;

    int m  = u & 63;
    int h  = u >> 6;
    int b0 = g * 8;

    for (int t = 0; t < TT; t++) {
        float bn[8], bd[8];
        if (red) {
            float4 snA = snum[(t*U + u)*2 + 0];
            float4 snB = snum[(t*U + u)*2 + 1];
            float4 sdA = sden[(t*U + u)*2 + 0];
            float4 sdB = sden[(t*U + u)*2 + 1];
            bn[0]=nc+snA.x; bn[1]=nc+snA.y; bn[2]=nc+snA.z; bn[3]=nc+snA.w;
            bn[4]=nc+snB.x; bn[5]=nc+snB.y; bn[6]=nc+snB.z; bn[7]=nc+snB.w;
            bd[0]=dc+sdA.x; bd[1]=dc+sdA.y; bd[2]=dc+sdA.z; bd[3]=dc+sdA.w;
            bd[4]=dc+sdB.x; bd[5]=dc+sdB.y; bd[6]=dc+sdB.z; bd[7]=dc+sdB.w;
        }

        #pragma unroll 1
        for (int f = 0; f < NUNF; f++) {
            // --- compute phase: exact myK iterations, branch-free body ---
            const float4* va = vA[cur];
            const float4* vb = vB[cur];
            float n0=0.f,n1=0.f,n2=0.f,n3=0.f,n4=0.f,n5=0.f,n6=0.f,n7=0.f;
            float d0=0.f,d1=0.f,d2=0.f,d3=0.f,d4=0.f,d5=0.f,d6=0.f,d7=0.f;
            #pragma unroll 2
            for (int k = 0; k < myK; k++) {
                float4 W = __ldg(&syn[k*U + u]);
                int j = __float_as_int(W.w);
                float4 aJ = va[j];
                float4 bJ = vb[j];
                float hz = fabsf(W.z);
                float t0 = fast_tanh(fmaf(aJ.x, W.x, W.y));
                float t1 = fast_tanh(fmaf(aJ.y, W.x, W.y));
                float t2 = fast_tanh(fmaf(aJ.z, W.x, W.y));
                float t3 = fast_tanh(fmaf(aJ.w, W.x, W.y));
                float t4 = fast_tanh(fmaf(bJ.x, W.x, W.y));
                float t5 = fast_tanh(fmaf(bJ.y, W.x, W.y));
                float t6 = fast_tanh(fmaf(bJ.z, W.x, W.y));
                float t7 = fast_tanh(fmaf(bJ.w, W.x, W.y));
                n0 = fmaf(W.z, t0, n0); d0 = fmaf(hz, t0, d0);
                n1 = fmaf(W.z, t1, n1); d1 = fmaf(hz, t1, d1);
                n2 = fmaf(W.z, t2, n2); d2 = fmaf(hz, t2, d2);
                n3 = fmaf(W.z, t3, n3); d3 = fmaf(hz, t3, d3);
                n4 = fmaf(W.z, t4, n4); d4 = fmaf(hz, t4, d4);
                n5 = fmaf(W.z, t5, n5); d5 = fmaf(hz, t5, d5);
                n6 = fmaf(W.z, t6, n6); d6 = fmaf(hz, t6, d6);
                n7 = fmaf(W.z, t7, n7); d7 = fmaf(hz, t7, d7);
            }
            s_part[u][kh*4 + 0] = make_float4(n0, n1, n2, n3);
            s_part[u][kh*4 + 1] = make_float4(n4, n5, n6, n7);
            s_part[u][kh*4 + 2] = make_float4(d0, d1, d2, d3);
            s_part[u][kh*4 + 3] = make_float4(d4, d5, d6, d7);
            __syncthreads();

            // --- reduce phase: reducer warps combine 4 partials, update v ---
            if (red) {
                float4 vuA = vA[cur][u];
                float4 vuB = vB[cur][u];
                float N0 = fmaf(cmt, vuA.x, bn[0]);
                float N1 = fmaf(cmt, vuA.y, bn[1]);
                float N2 = fmaf(cmt, vuA.z, bn[2]);
                float N3 = fmaf(cmt, vuA.w, bn[3]);
                float N4 = fmaf(cmt, vuB.x, bn[4]);
                float N5 = fmaf(cmt, vuB.y, bn[5]);
                float N6 = fmaf(cmt, vuB.z, bn[6]);
                float N7 = fmaf(cmt, vuB.w, bn[7]);
                float D0=bd[0],D1=bd[1],D2=bd[2],D3=bd[3];
                float D4=bd[4],D5=bd[5],D6=bd[6],D7=bd[7];
                #pragma unroll
                for (int p = 0; p < KSPLIT; p++) {
                    float4 a = s_part[u][p*4 + 0];
                    float4 b = s_part[u][p*4 + 1];
                    float4 c = s_part[u][p*4 + 2];
                    float4 d = s_part[u][p*4 + 3];
                    N0 += a.x; N1 += a.y; N2 += a.z; N3 += a.w;
                    N4 += b.x; N5 += b.y; N6 += b.z; N7 += b.w;
                    D0 += c.x; D1 += c.y; D2 += c.z; D3 += c.w;
                    D4 += d.x; D5 += d.y; D6 += d.z; D7 += d.w;
                }
                float4 wAo, wBo;
                wAo.x = N0 * fast_rcp(D0 + EPSF);
                wAo.y = N1 * fast_rcp(D1 + EPSF);
                wAo.z = N2 * fast_rcp(D2 + EPSF);
                wAo.w = N3 * fast_rcp(D3 + EPSF);
                wBo.x = N4 * fast_rcp(D4 + EPSF);
                wBo.y = N5 * fast_rcp(D5 + EPSF);
                wBo.z = N6 * fast_rcp(D6 + EPSF);
                wBo.w = N7 * fast_rcp(D7 + EPSF);
                vA[cur ^ 1][u] = wAo;
                vB[cur ^ 1][u] = wBo;
            }
            __syncthreads();
            cur ^= 1;
        }

        // coalesced motor-output write (reducer warps; gather through slot map)
        if (red) {
            int ms = s_mslot[m];
            float4 vv = (h == 0) ? vA[cur][ms] : vB[cur][ms];
            float ww = s_ow[m], bb = s_ob[m];
            g_outs[((b0 + 4*h + 0)*TT + t)*MOTOR + m] = fmaf(vv.x, ww, bb);
            g_outs[((b0 + 4*h + 1)*TT + t)*MOTOR + m] = fmaf(vv.y, ww, bb);
            g_outs[((b0 + 4*h + 2)*TT + t)*MOTOR + m] = fmaf(vv.z, ww, bb);
            g_outs[((b0 + 4*h + 3)*TT + t)*MOTOR + m] = fmaf(vv.w, ww, bb);
        }
    }
}

// ---------------- attention pooling + classifier ----------------------------
__global__ void __launch_bounds__(128) attn_kernel(
    const float* __restrict__ aw1, const float* __restrict__ ab1,
    const float* __restrict__ aw2, const float* __restrict__ cw1,
    const float* __restrict__ cb1, const float* __restrict__ cw2,
    const float* __restrict__ cb2, float* __restrict__ out)
{
    __shared__ float so[TT][MOTOR+1];
    __shared__ float w1[MOTOR*32];
    __shared__ float sc[TT];
    __shared__ float ctx[MOTOR];
    __shared__ float hid[128];

    int b = blockIdx.x, tid = threadIdx.x;

    for (int i = tid; i < TT*MOTOR; i += 128)
        so[i/MOTOR][i%MOTOR] = g_outs[b*TT*MOTOR + i];
    for (int i = tid; i < MOTOR*32; i += 128)
        w1[i] = aw1[i];
    __syncthreads();

    if (tid < TT) {
        float acc = 0.f;
        for (int hh = 0; hh < 32; hh++) {
            float s = ab1[hh];
            #pragma unroll 8
            for (int uu = 0; uu < MOTOR; uu++)
                s = fmaf(so[tid][uu], w1[uu*32 + hh], s);
            s = fmaxf(s, 0.f);
            acc = fmaf(s, aw2[hh], acc);
        }
        sc[tid] = acc;
    }
    __syncthreads();

    if (tid == 0) {
        float mm = -1e30f;
        for (int t = 0; t < TT; t++) mm = fmaxf(mm, sc[t]);
        float s = 0.f;
        for (int t = 0; t < TT; t++) { float e = __expf(sc[t]-mm); sc[t] = e; s += e; }
        float invs = 1.f / s;
        for (int t = 0; t < TT; t++) sc[t] *= invs;
    }
    __syncthreads();

    if (tid < MOTOR) {
        float a = 0.f;
        for (int t = 0; t < TT; t++) a = fmaf(sc[t], so[t][tid], a);
        ctx[tid] = a;
    }
    __syncthreads();

    {
        float s = cb1[tid];
        for (int uu = 0; uu < MOTOR; uu++)
            s = fmaf(ctx[uu], cw1[uu*128 + tid], s);
        hid[tid] = fmaxf(s, 0.f);
    }
    __syncthreads();

    if (tid < NCLS) {
        float s = cb2[tid];
        for (int hh = 0; hh < 128; hh++)
            s = fmaf(hid[hh], cw2[hh*NCLS + tid], s);
        out[b*NCLS + tid] = s;
    }
}

// ---------------- launch ----------------------------------------------------
extern "C" void kernel_launch(void* const* d_in, const int* in_sizes, int n_in,
                              void* d_out, int out_size)
{
    const float* x        = (const float*)d_in[0];
    const float* ln_g     = (const float*)d_in[1];
    const float* ln_b     = (const float*)d_in[2];
    const float* gleak    = (const float*)d_in[3];
    const float* vleak    = (const float*)d_in[4];
    const float* cm       = (const float*)d_in[5];
    const float* sigma    = (const float*)d_in[6];
    const float* mu       = (const float*)d_in[7];
    const float* w        = (const float*)d_in[8];
    const float* erev     = (const float*)d_in[9];
    const float* ssig     = (const float*)d_in[10];
    const float* smu      = (const float*)d_in[11];
    const float* sw       = (const float*)d_in[12];
    const float* serev    = (const float*)d_in[13];
    const float* in_w     = (const float*)d_in[14];
    const float* in_b     = (const float*)d_in[15];
    const float* out_w    = (const float*)d_in[16];
    const float* out_b    = (const float*)d_in[17];
    const float* aw1      = (const float*)d_in[18];
    const float* ab1      = (const float*)d_in[19];
    const float* aw2      = (const float*)d_in[20];
    const float* cw1      = (const float*)d_in[21];
    const float* cb1      = (const float*)d_in[22];
    const float* cw2      = (const float*)d_in[23];
    const float* cb2      = (const float*)d_in[24];
    const float* mask     = (const float*)d_in[25];
    const float* smask    = (const float*)d_in[26];

    prep_kernel<<<1, U>>>(gleak, vleak, cm, sigma, mu, w, erev,
                          ssig, smu, sw, serev, mask, smask);
    sens_kernel<<<dim3(TT, NG8), U>>>(x, ln_g, ln_b, in_w, in_b);
    ltc_main<<<NG8, 512>>>(out_w, out_b);
    attn_kernel<<<BATCH, 128>>>(aw1, ab1, aw2, cw1, cb1, cw2, cb2, (float*)d_out);
}